// round 8
// baseline (speedup 1.0000x reference)
#include <cuda_runtime.h>
#include <cstdint>

// out[c,t,x,y] = mc ? k[t] : mp ? 0.5*k[t-1] : mn ? 0.25*k[t+1] : 0   (cases exclusive)
//
// Single fused kernel. Each CTA owns all 32 channels x 8 float4-groups:
//   - prologue stages mask slice (64t x 8g, zero-padded t=-1/64) into smem (1x read)
//   - 128 threads pack 2-bit selector codes into smem words [w][g] (t=4w..4w+3)
//   - main loop: rolling-register 1-load/1-store stream, selector via LDS broadcast

#define ALPHA 0.5f
#define BETA  0.25f

constexpr int NC = 32;
constexpr int NT = 64;
constexpr int PLANE4 = 256 * 256 / 4;   // 16384 float4 groups per t-slice
constexpr int NGB = 8;                  // float4-groups per CTA (128 B of plane)
constexpr int NCTA = PLANE4 / NGB;      // 2048 CTAs
constexpr int NW = NT / 4;              // 16 selector words per group

__device__ __forceinline__ uint32_t code1(int mc, int mp, int mn) {
    return mc ? 1u : (mp ? 2u : (mn ? 3u : 0u));
}

__device__ __forceinline__ float pick(uint32_t c, float kc, float kp, float kn) {
    return (c == 1u) ? kc
         : (c == 2u) ? ALPHA * kp
         : (c == 3u) ? BETA * kn
         : 0.0f;
}

__global__ void __launch_bounds__(256, 8)
dsb_fused(const float4* __restrict__ k,
          const int4*   __restrict__ mask,
          float4*       __restrict__ out)
{
    // smask[ti][gl] holds mask[t = ti-1]; rows 0 and NT+1 are zero pads.
    __shared__ int4     smask[NT + 2][NGB];   // 8448 B
    __shared__ uint32_t ssel[NW][NGB];        //  512 B

    const int tid = threadIdx.x;
    const int g0  = blockIdx.x * NGB;

    // ---- prologue: stage mask (each CTA reads its slice exactly once) ----
    {
        const int gl = tid & (NGB - 1);
        const int t  = tid >> 3;              // 0..31
        smask[1 + t][gl]      = __ldg(&mask[t * PLANE4 + g0 + gl]);
        smask[1 + t + 32][gl] = __ldg(&mask[(t + 32) * PLANE4 + g0 + gl]);
        if (tid < NGB)            smask[0][tid]          = make_int4(0, 0, 0, 0);
        else if (tid < 2 * NGB)   smask[NT + 1][tid - 8] = make_int4(0, 0, 0, 0);
    }
    __syncthreads();

    // ---- pack selector words: thread j -> (w = j/8, gl = j%8) ----
    if (tid < NW * NGB) {
        const int gl = tid & (NGB - 1);
        const int w  = tid >> 3;              // 0..15
        const int t0 = 4 * w;
        uint32_t word = 0u;
        #pragma unroll
        for (int i = 0; i < 4; i++) {
            const int4 mp = smask[t0 + i][gl];
            const int4 mc = smask[t0 + i + 1][gl];
            const int4 mn = smask[t0 + i + 2][gl];
            uint32_t byte =  code1(mc.x, mp.x, mn.x)
                          | (code1(mc.y, mp.y, mn.y) << 2)
                          | (code1(mc.z, mp.z, mn.z) << 4)
                          | (code1(mc.w, mp.w, mn.w) << 6);
            word |= byte << (i * 8);
        }
        ssel[w][gl] = word;
    }
    __syncthreads();

    // ---- main stream: thread (c = tid/8, gl = tid%8) walks t ----
    const int gl = tid & (NGB - 1);
    const int c  = tid >> 3;

    const float4* kk = k   + (size_t)c * NT * PLANE4 + g0 + gl;
    float4*       oo = out + (size_t)c * NT * PLANE4 + g0 + gl;

    float4 kp = make_float4(0.f, 0.f, 0.f, 0.f);
    float4 kc = __ldcs(kk);

    int t = 0;
    #pragma unroll 1
    for (int w = 0; w < NW; w++) {
        const uint32_t wrd = ssel[w][gl];     // LDS.32, broadcast over c
        #pragma unroll
        for (int tt = 0; tt < 4; tt++) {
            float4 kn = (t < NT - 1) ? __ldcs(kk + (t + 1) * PLANE4)
                                     : make_float4(0.f, 0.f, 0.f, 0.f);

            const uint32_t byte = (wrd >> (tt * 8)) & 0xFFu;
            float4 o;
            o.x = pick( byte       & 3u, kc.x, kp.x, kn.x);
            o.y = pick((byte >> 2) & 3u, kc.y, kp.y, kn.y);
            o.z = pick((byte >> 4) & 3u, kc.z, kp.z, kn.z);
            o.w = pick((byte >> 6) & 3u, kc.w, kp.w, kn.w);

            __stcs(oo + t * PLANE4, o);

            kp = kc; kc = kn;
            t++;
        }
    }
}

extern "C" void kernel_launch(void* const* d_in, const int* in_sizes, int n_in,
                              void* d_out, int out_size)
{
    const float4* k    = (const float4*)d_in[0];
    const int4*   mask = (const int4*)d_in[1];
    float4*       out  = (float4*)d_out;

    dsb_fused<<<NCTA, 256>>>(k, mask, out);
}

// round 9
// speedup vs baseline: 1.1155x; 1.1155x over previous
#include <cuda_runtime.h>
#include <cstdint>

// out[c,t,x,y] = mc ? k[t] : mp ? 0.5*k[t-1] : mn ? 0.25*k[t+1] : 0   (cases exclusive)
//
// Single fused kernel, locality-preserving mapping:
//   CTA = 4 channels x 64 consecutive float4-groups (256 threads).
//   Prologue: compute 2-bit selector words (16 w x 64 g) from mask into 4 KB
//   smem — mask is read 8x chip-wide (L2 hits, ~130 MB), trading cheap L2
//   headroom for zero pre-kernel / zero launch gap.
//   Stream: rolling-register 1-load/1-store walk over t; each warp's access
//   is one contiguous 512 B line (same DRAM locality as the 2-kernel best).

#define ALPHA 0.5f
#define BETA  0.25f

constexpr int NC  = 32;
constexpr int NT  = 64;
constexpr int PLANE4 = 256 * 256 / 4;   // 16384 float4 groups per t-slice
constexpr int CPB = 4;                  // channels per CTA
constexpr int GPB = 64;                 // float4-groups per CTA
constexpr int NW  = NT / 4;             // 16 selector words per group
constexpr int NCTA = (PLANE4 / GPB) * (NC / CPB);   // 256 * 8 = 2048

__device__ __forceinline__ uint32_t code1(int mc, int mp, int mn) {
    return mc ? 1u : (mp ? 2u : (mn ? 3u : 0u));
}

__device__ __forceinline__ float pick(uint32_t c, float kc, float kp, float kn) {
    return (c == 1u) ? kc
         : (c == 2u) ? ALPHA * kp
         : (c == 3u) ? BETA * kn
         : 0.0f;
}

__global__ void __launch_bounds__(256, 8)
dsb_fused(const float4* __restrict__ k,
          const int4*   __restrict__ mask,
          float4*       __restrict__ out)
{
    __shared__ uint32_t ssel[NW][GPB];     // 4 KB

    const int tid = threadIdx.x;
    const int bx  = blockIdx.x;
    const int g0  = (bx & 255) * GPB;      // 256 g-blocks per channel-block
    const int c0  = (bx >> 8) * CPB;

    // ---- prologue: selector words. 1024 tasks (w, gl), 4 per thread.
    // Consecutive threads -> consecutive gl -> coalesced 1 KB mask loads.
    #pragma unroll
    for (int batch = 0; batch < NW * GPB / 256; batch++) {
        const int task = batch * 256 + tid;
        const int gl = task & (GPB - 1);
        const int w  = task >> 6;           // 0..15
        const int t0 = 4 * w;

        int4 mbuf[6];
        #pragma unroll
        for (int i = 0; i < 6; i++) {
            const int t = t0 - 1 + i;
            mbuf[i] = (t >= 0 && t < NT)
                    ? __ldg(&mask[t * PLANE4 + g0 + gl])
                    : make_int4(0, 0, 0, 0);
        }
        uint32_t word = 0u;
        #pragma unroll
        for (int i = 0; i < 4; i++) {
            const int4 mp = mbuf[i];
            const int4 mc = mbuf[i + 1];
            const int4 mn = mbuf[i + 2];
            uint32_t byte =  code1(mc.x, mp.x, mn.x)
                          | (code1(mc.y, mp.y, mn.y) << 2)
                          | (code1(mc.z, mp.z, mn.z) << 4)
                          | (code1(mc.w, mp.w, mn.w) << 6);
            word |= byte << (i * 8);
        }
        ssel[w][gl] = word;
    }

    // ---- stream setup (independent of ssel; overlaps prologue latency) ----
    const int gl = tid & (GPB - 1);
    const int cl = tid >> 6;               // 0..3
    const int c  = c0 + cl;

    const float4* kk = k   + (size_t)c * NT * PLANE4 + g0 + gl;
    float4*       oo = out + (size_t)c * NT * PLANE4 + g0 + gl;

    float4 kp = make_float4(0.f, 0.f, 0.f, 0.f);
    float4 kc = __ldcs(kk);

    __syncthreads();

    // ---- main stream: rolling registers over t ----
    int t = 0;
    #pragma unroll 1
    for (int w = 0; w < NW; w++) {
        const uint32_t wrd = ssel[w][gl];   // LDS.32, conflict-free
        #pragma unroll
        for (int tt = 0; tt < 4; tt++) {
            float4 kn = (t < NT - 1) ? __ldcs(kk + (t + 1) * PLANE4)
                                     : make_float4(0.f, 0.f, 0.f, 0.f);

            const uint32_t byte = (wrd >> (tt * 8)) & 0xFFu;
            float4 o;
            o.x = pick( byte       & 3u, kc.x, kp.x, kn.x);
            o.y = pick((byte >> 2) & 3u, kc.y, kp.y, kn.y);
            o.z = pick((byte >> 4) & 3u, kc.z, kp.z, kn.z);
            o.w = pick((byte >> 6) & 3u, kc.w, kp.w, kn.w);

            __stcs(oo + t * PLANE4, o);

            kp = kc; kc = kn;
            t++;
        }
    }
}

extern "C" void kernel_launch(void* const* d_in, const int* in_sizes, int n_in,
                              void* d_out, int out_size)
{
    const float4* k    = (const float4*)d_in[0];
    const int4*   mask = (const int4*)d_in[1];
    float4*       out  = (float4*)d_out;

    dsb_fused<<<NCTA, 256>>>(k, mask, out);
}